// round 2
// baseline (speedup 1.0000x reference)
#include <cuda_runtime.h>
#include <cuda_bf16.h>

#define N_MAX 100000
#define E_MAX 1000000
#define F 64
#define ALPHA 0.2f

// Scratch (static __device__ allocation — no cudaMalloc allowed)
__device__ float g_Wh[N_MAX * F];     // 25.6 MB
__device__ float g_ssrc[N_MAX];
__device__ float g_sdst[N_MAX];
__device__ float g_denom[N_MAX];
__device__ float g_ex[E_MAX];         // 4 MB

// ---------------------------------------------------------------------------
// K0: zero output + denom
// ---------------------------------------------------------------------------
__global__ void zero_kernel(float* __restrict__ out, int n_out, int n_nodes) {
    int stride = gridDim.x * blockDim.x;
    for (int i = blockIdx.x * blockDim.x + threadIdx.x; i < n_out; i += stride)
        out[i] = 0.0f;
    for (int i = blockIdx.x * blockDim.x + threadIdx.x; i < n_nodes; i += stride)
        g_denom[i] = 0.0f;
}

// ---------------------------------------------------------------------------
// K1: Wh = h @ W^T + Wb ; s_src = Wh @ a[:F] ; s_dst = Wh @ a[F:]
// One warp per node. W held transposed in smem (conflict-free inner loop).
// ---------------------------------------------------------------------------
__global__ void __launch_bounds__(256) wh_kernel(
    const float* __restrict__ h, const float* __restrict__ W,
    const float* __restrict__ Wb, const float* __restrict__ a, int n_nodes)
{
    __shared__ float Wt[F][F + 1];   // Wt[k][j] = W[j][k]
    __shared__ float sWb[F];
    __shared__ float sa[2 * F];
    __shared__ float hrow[8][F];

    int tid = threadIdx.x;
    // cooperative load of W (transposed), Wb, a
    for (int i = tid; i < F * F; i += 256) {
        int j = i >> 6, k = i & 63;
        Wt[k][j] = W[i];
    }
    if (tid < F) sWb[tid] = Wb[tid];
    if (tid < 2 * F) sa[tid] = a[tid];
    __syncthreads();

    int warp = tid >> 5;
    int lane = tid & 31;
    int n = blockIdx.x * 8 + warp;
    if (n >= n_nodes) return;

    // load h row into smem (broadcast-friendly reads in the k-loop)
    hrow[warp][lane]      = h[n * F + lane];
    hrow[warp][lane + 32] = h[n * F + lane + 32];
    __syncwarp();

    float acc0 = 0.0f, acc1 = 0.0f;
    #pragma unroll
    for (int k = 0; k < F; k++) {
        float hk = hrow[warp][k];
        acc0 = fmaf(hk, Wt[k][lane],      acc0);
        acc1 = fmaf(hk, Wt[k][lane + 32], acc1);
    }
    acc0 += sWb[lane];
    acc1 += sWb[lane + 32];

    g_Wh[n * F + lane]      = acc0;
    g_Wh[n * F + lane + 32] = acc1;

    // per-node attention scores
    float p = acc0 * sa[lane]     + acc1 * sa[lane + 32];        // a_src
    float q = acc0 * sa[F + lane] + acc1 * sa[F + lane + 32];    // a_dst
    #pragma unroll
    for (int o = 16; o > 0; o >>= 1) {
        p += __shfl_down_sync(0xffffffffu, p, o);
        q += __shfl_down_sync(0xffffffffu, q, o);
    }
    if (lane == 0) {
        g_ssrc[n] = p;
        g_sdst[n] = q;
    }
}

// ---------------------------------------------------------------------------
// K2: per edge — e = leaky_relu(s_src[src]+s_dst[dst]+ab); ex = exp(e);
//     denom[dst] += ex.  (Max-shift skipped: mathematically cancels in attn,
//     and |e| is tiny for these inputs so no overflow risk.)
// ---------------------------------------------------------------------------
__global__ void __launch_bounds__(256) edge_exp_kernel(
    const int* __restrict__ src, const int* __restrict__ dst,
    const float* __restrict__ ab_p, int n_edges)
{
    float ab = __ldg(ab_p);
    int stride = gridDim.x * blockDim.x;
    for (int i = blockIdx.x * blockDim.x + threadIdx.x; i < n_edges; i += stride) {
        int s = src[i];
        int d = dst[i];
        float x = g_ssrc[s] + g_sdst[d] + ab;
        x = (x > 0.0f) ? x : ALPHA * x;
        float ex = expf(x);
        g_ex[i] = ex;
        atomicAdd(&g_denom[d], ex);
    }
}

// ---------------------------------------------------------------------------
// K3: out[dst] += (ex/denom[dst]) * Wh[src]
// Half-warp per edge; one red.global.add.v4.f32 per lane (16 per edge).
// ---------------------------------------------------------------------------
__global__ void __launch_bounds__(256) aggregate_kernel(
    const int* __restrict__ src, const int* __restrict__ dst,
    float* __restrict__ out, int n_edges)
{
    int gwarp = (blockIdx.x * blockDim.x + threadIdx.x) >> 5;
    int lane  = threadIdx.x & 31;
    int half  = lane >> 4;          // 0 or 1: which edge within the warp
    int l16   = lane & 15;          // float4 slot within the edge (16 x f4 = 64 f)

    int e = gwarp * 2 + half;
    if (e >= n_edges) return;

    int s = src[e];
    int d = dst[e];
    float attn = g_ex[e] / g_denom[d];   // denom > 0 whenever edge e exists

    const float4* wh4 = reinterpret_cast<const float4*>(g_Wh) + (size_t)s * 16 + l16;
    float4 v = __ldg(wh4);
    v.x *= attn; v.y *= attn; v.z *= attn; v.w *= attn;

    float4* o = reinterpret_cast<float4*>(out) + (size_t)d * 16 + l16;
    asm volatile("red.global.add.v4.f32 [%0], {%1, %2, %3, %4};"
                 :: "l"(o), "f"(v.x), "f"(v.y), "f"(v.z), "f"(v.w)
                 : "memory");
}

// ---------------------------------------------------------------------------
extern "C" void kernel_launch(void* const* d_in, const int* in_sizes, int n_in,
                              void* d_out, int out_size) {
    const float* h   = (const float*)d_in[0];
    const float* W   = (const float*)d_in[1];
    const float* Wb  = (const float*)d_in[2];
    const float* a   = (const float*)d_in[3];
    const float* ab  = (const float*)d_in[4];
    const int*   src = (const int*)d_in[5];
    const int*   dst = (const int*)d_in[6];
    float* out = (float*)d_out;

    int n_nodes = in_sizes[0] / F;
    int n_edges = in_sizes[5];

    zero_kernel<<<512, 256>>>(out, out_size, n_nodes);
    wh_kernel<<<(n_nodes + 7) / 8, 256>>>(h, W, Wb, a, n_nodes);
    edge_exp_kernel<<<(n_edges + 255) / 256, 256>>>(src, dst, ab, n_edges);
    aggregate_kernel<<<(n_edges + 15) / 16, 256>>>(src, dst, out, n_edges);
}

// round 3
// speedup vs baseline: 1.2412x; 1.2412x over previous
#include <cuda_runtime.h>
#include <cuda_bf16.h>

#define N_MAX 100000
#define E_MAX 1000000
#define F 64
#define ALPHA 0.2f

// Scratch (static __device__ allocation — no cudaMalloc allowed)
__device__ float g_Wh[N_MAX * F];     // 25.6 MB
__device__ float g_ssrc[N_MAX];
__device__ float g_sdst[N_MAX];
__device__ float g_denom[N_MAX];

// ---------------------------------------------------------------------------
// K0: zero output + denom
// ---------------------------------------------------------------------------
__global__ void zero_kernel(float* __restrict__ out, int n_out, int n_nodes) {
    int stride = gridDim.x * blockDim.x;
    for (int i = blockIdx.x * blockDim.x + threadIdx.x; i < n_out; i += stride)
        out[i] = 0.0f;
    for (int i = blockIdx.x * blockDim.x + threadIdx.x; i < n_nodes; i += stride)
        g_denom[i] = 0.0f;
}

// ---------------------------------------------------------------------------
// K1: Wh = h @ W^T + Wb ; s_src = Wh @ a[:F] ; s_dst = Wh @ a[F:]
// 4 nodes per warp; h rows live in registers, broadcast via shfl;
// W^T rows from smem (2 LDS amortized over 4 nodes / 8 FMAs per k-step).
// ---------------------------------------------------------------------------
__global__ void __launch_bounds__(256) wh_kernel(
    const float* __restrict__ h, const float* __restrict__ W,
    const float* __restrict__ Wb, const float* __restrict__ a, int n_nodes)
{
    __shared__ float Wt[F][F + 1];   // Wt[k][j] = W[j][k]
    __shared__ float sWb[F];
    __shared__ float sa[2 * F];

    int tid = threadIdx.x;
    for (int i = tid; i < F * F; i += 256) {
        int j = i >> 6, k = i & 63;
        Wt[k][j] = W[i];
    }
    if (tid < F) sWb[tid] = Wb[tid];
    if (tid < 2 * F) sa[tid] = a[tid];
    __syncthreads();

    int warp = tid >> 5;
    int lane = tid & 31;
    int n0 = (blockIdx.x * 8 + warp) * 4;
    if (n0 >= n_nodes) return;

    // h rows for 4 nodes in registers
    float hr0[4], hr1[4];
    #pragma unroll
    for (int i = 0; i < 4; i++) {
        int n = min(n0 + i, n_nodes - 1);
        hr0[i] = h[(size_t)n * F + lane];
        hr1[i] = h[(size_t)n * F + lane + 32];
    }

    float acc0[4] = {0.f, 0.f, 0.f, 0.f};
    float acc1[4] = {0.f, 0.f, 0.f, 0.f};

    #pragma unroll
    for (int k = 0; k < 32; k++) {
        float w0 = Wt[k][lane];
        float w1 = Wt[k][lane + 32];
        #pragma unroll
        for (int i = 0; i < 4; i++) {
            float hk = __shfl_sync(0xffffffffu, hr0[i], k);
            acc0[i] = fmaf(hk, w0, acc0[i]);
            acc1[i] = fmaf(hk, w1, acc1[i]);
        }
    }
    #pragma unroll
    for (int k = 0; k < 32; k++) {
        float w0 = Wt[k + 32][lane];
        float w1 = Wt[k + 32][lane + 32];
        #pragma unroll
        for (int i = 0; i < 4; i++) {
            float hk = __shfl_sync(0xffffffffu, hr1[i], k);
            acc0[i] = fmaf(hk, w0, acc0[i]);
            acc1[i] = fmaf(hk, w1, acc1[i]);
        }
    }

    float b0 = sWb[lane], b1 = sWb[lane + 32];
    float as0 = sa[lane], as1 = sa[lane + 32];
    float ad0 = sa[F + lane], ad1 = sa[F + lane + 32];

    #pragma unroll
    for (int i = 0; i < 4; i++) {
        int n = n0 + i;
        if (n >= n_nodes) break;
        float v0 = acc0[i] + b0;
        float v1 = acc1[i] + b1;
        g_Wh[(size_t)n * F + lane]      = v0;
        g_Wh[(size_t)n * F + lane + 32] = v1;

        float p = v0 * as0 + v1 * as1;   // a_src score
        float q = v0 * ad0 + v1 * ad1;   // a_dst score
        #pragma unroll
        for (int o = 16; o > 0; o >>= 1) {
            p += __shfl_down_sync(0xffffffffu, p, o);
            q += __shfl_down_sync(0xffffffffu, q, o);
        }
        if (lane == 0) {
            g_ssrc[n] = p;
            g_sdst[n] = q;
        }
    }
}

// ---------------------------------------------------------------------------
// K2 (fused): per edge — ex = exp(lrelu(s_src[src]+s_dst[dst]+ab));
//   denom[dst] += ex;  out[dst] += ex * Wh[src]   (unnormalized accumulate)
// Half-warp per edge; one red.global.add.v4.f32 per lane (16 per edge).
// Max-shift skipped: exactly cancels in attn = ex/denom; |e| is small here.
// ---------------------------------------------------------------------------
__global__ void __launch_bounds__(256) edge_fused_kernel(
    const int* __restrict__ src, const int* __restrict__ dst,
    const float* __restrict__ ab_p, float* __restrict__ out, int n_edges)
{
    float ab = __ldg(ab_p);
    int gwarp = (blockIdx.x * blockDim.x + threadIdx.x) >> 5;
    int lane  = threadIdx.x & 31;
    int half  = lane >> 4;          // which edge within the warp
    int l16   = lane & 15;          // float4 slot within the edge

    int e = gwarp * 2 + half;
    bool valid = (e < n_edges);
    int ec = valid ? e : 0;

    int s = __ldg(&src[ec]);
    int d = __ldg(&dst[ec]);

    float ex = 0.0f;
    if (l16 == 0 && valid) {
        float x = g_ssrc[s] + g_sdst[d] + ab;
        x = (x > 0.0f) ? x : ALPHA * x;
        ex = expf(x);
        atomicAdd(&g_denom[d], ex);
    }
    ex = __shfl_sync(0xffffffffu, ex, half * 16);

    if (valid) {
        const float4* wh4 = reinterpret_cast<const float4*>(g_Wh) + (size_t)s * 16 + l16;
        float4 v = __ldg(wh4);
        v.x *= ex; v.y *= ex; v.z *= ex; v.w *= ex;
        float4* o = reinterpret_cast<float4*>(out) + (size_t)d * 16 + l16;
        asm volatile("red.global.add.v4.f32 [%0], {%1, %2, %3, %4};"
                     :: "l"(o), "f"(v.x), "f"(v.y), "f"(v.z), "f"(v.w)
                     : "memory");
    }
}

// ---------------------------------------------------------------------------
// K3: normalize — out[n] /= (denom[n] > 0 ? denom[n] : 1)
// One thread per float4 (16 threads per node row).
// ---------------------------------------------------------------------------
__global__ void __launch_bounds__(256) normalize_kernel(
    float* __restrict__ out, int n_nodes)
{
    int idx = blockIdx.x * blockDim.x + threadIdx.x;   // float4 index
    int total = n_nodes * 16;
    if (idx >= total) return;
    int n = idx >> 4;
    float den = g_denom[n];
    float r = (den > 0.0f) ? (1.0f / den) : 1.0f;
    float4* o = reinterpret_cast<float4*>(out) + idx;
    float4 v = *o;
    v.x *= r; v.y *= r; v.z *= r; v.w *= r;
    *o = v;
}

// ---------------------------------------------------------------------------
extern "C" void kernel_launch(void* const* d_in, const int* in_sizes, int n_in,
                              void* d_out, int out_size) {
    const float* h   = (const float*)d_in[0];
    const float* W   = (const float*)d_in[1];
    const float* Wb  = (const float*)d_in[2];
    const float* a   = (const float*)d_in[3];
    const float* ab  = (const float*)d_in[4];
    const int*   src = (const int*)d_in[5];
    const int*   dst = (const int*)d_in[6];
    float* out = (float*)d_out;

    int n_nodes = in_sizes[0] / F;
    int n_edges = in_sizes[5];

    zero_kernel<<<512, 256>>>(out, out_size, n_nodes);
    wh_kernel<<<(n_nodes + 31) / 32, 256>>>(h, W, Wb, a, n_nodes);
    edge_fused_kernel<<<(n_edges + 15) / 16, 256>>>(src, dst, ab, out, n_edges);
    normalize_kernel<<<(n_nodes * 16 + 255) / 256, 256>>>(out, n_nodes);
}

// round 4
// speedup vs baseline: 1.3763x; 1.1089x over previous
#include <cuda_runtime.h>
#include <cuda_bf16.h>

#define N_MAX 100000
#define E_MAX 1000000
#define F 64
#define ALPHA 0.2f

// Scratch (static __device__ allocation — no cudaMalloc allowed)
__device__ float g_Wh[N_MAX * F];       // 25.6 MB (L2-resident)
__device__ float g_ssrc[N_MAX];
__device__ float g_sdst[N_MAX];
__device__ int   g_cnt[N_MAX];          // per-dst edge count
__device__ int   g_off[N_MAX];          // CSR base offset per dst
__device__ int   g_cur[N_MAX];          // scatter cursor per dst
__device__ int   g_cursor;              // global CSR allocation cursor
__device__ int2  g_rec[E_MAX];          // packed (src, ex-bits) per edge, dst-grouped

// ---------------------------------------------------------------------------
// K0: zero counters + global cursor
// ---------------------------------------------------------------------------
__global__ void zero_kernel(int n_nodes) {
    int i = blockIdx.x * blockDim.x + threadIdx.x;
    if (i < n_nodes) g_cnt[i] = 0;
    if (i == 0) g_cursor = 0;
}

// ---------------------------------------------------------------------------
// K1: Wh = h @ W^T + Wb ; s_src = Wh @ a[:F] ; s_dst = Wh @ a[F:]
// 4 nodes per warp; h rows in registers, broadcast via shfl.
// ---------------------------------------------------------------------------
__global__ void __launch_bounds__(256) wh_kernel(
    const float* __restrict__ h, const float* __restrict__ W,
    const float* __restrict__ Wb, const float* __restrict__ a, int n_nodes)
{
    __shared__ float Wt[F][F + 1];   // Wt[k][j] = W[j][k]
    __shared__ float sWb[F];
    __shared__ float sa[2 * F];

    int tid = threadIdx.x;
    for (int i = tid; i < F * F; i += 256) {
        int j = i >> 6, k = i & 63;
        Wt[k][j] = W[i];
    }
    if (tid < F) sWb[tid] = Wb[tid];
    if (tid < 2 * F) sa[tid] = a[tid];
    __syncthreads();

    int warp = tid >> 5;
    int lane = tid & 31;
    int n0 = (blockIdx.x * 8 + warp) * 4;
    if (n0 >= n_nodes) return;

    float hr0[4], hr1[4];
    #pragma unroll
    for (int i = 0; i < 4; i++) {
        int n = min(n0 + i, n_nodes - 1);
        hr0[i] = h[(size_t)n * F + lane];
        hr1[i] = h[(size_t)n * F + lane + 32];
    }

    float acc0[4] = {0.f, 0.f, 0.f, 0.f};
    float acc1[4] = {0.f, 0.f, 0.f, 0.f};

    #pragma unroll
    for (int k = 0; k < 32; k++) {
        float w0 = Wt[k][lane];
        float w1 = Wt[k][lane + 32];
        #pragma unroll
        for (int i = 0; i < 4; i++) {
            float hk = __shfl_sync(0xffffffffu, hr0[i], k);
            acc0[i] = fmaf(hk, w0, acc0[i]);
            acc1[i] = fmaf(hk, w1, acc1[i]);
        }
    }
    #pragma unroll
    for (int k = 0; k < 32; k++) {
        float w0 = Wt[k + 32][lane];
        float w1 = Wt[k + 32][lane + 32];
        #pragma unroll
        for (int i = 0; i < 4; i++) {
            float hk = __shfl_sync(0xffffffffu, hr1[i], k);
            acc0[i] = fmaf(hk, w0, acc0[i]);
            acc1[i] = fmaf(hk, w1, acc1[i]);
        }
    }

    float b0 = sWb[lane], b1 = sWb[lane + 32];
    float as0 = sa[lane], as1 = sa[lane + 32];
    float ad0 = sa[F + lane], ad1 = sa[F + lane + 32];

    #pragma unroll
    for (int i = 0; i < 4; i++) {
        int n = n0 + i;
        if (n >= n_nodes) break;
        float v0 = acc0[i] + b0;
        float v1 = acc1[i] + b1;
        g_Wh[(size_t)n * F + lane]      = v0;
        g_Wh[(size_t)n * F + lane + 32] = v1;

        float p = v0 * as0 + v1 * as1;
        float q = v0 * ad0 + v1 * ad1;
        #pragma unroll
        for (int o = 16; o > 0; o >>= 1) {
            p += __shfl_down_sync(0xffffffffu, p, o);
            q += __shfl_down_sync(0xffffffffu, q, o);
        }
        if (lane == 0) {
            g_ssrc[n] = p;
            g_sdst[n] = q;
        }
    }
}

// ---------------------------------------------------------------------------
// K2: count edges per dst (int REDG, spread addresses)
// ---------------------------------------------------------------------------
__global__ void __launch_bounds__(256) count_kernel(
    const int* __restrict__ dst, int n_edges)
{
    int i = blockIdx.x * blockDim.x + threadIdx.x;
    if (i < n_edges) atomicAdd(&g_cnt[dst[i]], 1);
}

// ---------------------------------------------------------------------------
// K3: CSR offsets via warp-scan + one global-cursor atomic per warp.
// Segment placement order is arbitrary (nondeterministic) but each dst's
// edge set — and hence the output — is the same.
// ---------------------------------------------------------------------------
__global__ void __launch_bounds__(256) offset_kernel(int n_nodes) {
    int i = blockIdx.x * blockDim.x + threadIdx.x;
    int lane = threadIdx.x & 31;
    int c = (i < n_nodes) ? g_cnt[i] : 0;

    // inclusive warp scan
    int s = c;
    #pragma unroll
    for (int o = 1; o < 32; o <<= 1) {
        int t = __shfl_up_sync(0xffffffffu, s, o);
        if (lane >= o) s += t;
    }
    int warp_total = __shfl_sync(0xffffffffu, s, 31);
    int base = 0;
    if (lane == 31) base = atomicAdd(&g_cursor, warp_total);
    base = __shfl_sync(0xffffffffu, base, 31);

    if (i < n_nodes) {
        int off = base + s - c;   // exclusive within warp
        g_off[i] = off;
        g_cur[i] = off;
    }
}

// ---------------------------------------------------------------------------
// K4: scatter — ex = exp(lrelu(s_src[src]+s_dst[dst]+ab)); claim slot in
// dst segment; write packed (src, ex). Max-shift skipped (cancels exactly).
// ---------------------------------------------------------------------------
__global__ void __launch_bounds__(256) scatter_kernel(
    const int* __restrict__ src, const int* __restrict__ dst,
    const float* __restrict__ ab_p, int n_edges)
{
    int i = blockIdx.x * blockDim.x + threadIdx.x;
    if (i >= n_edges) return;
    float ab = __ldg(ab_p);
    int s = src[i];
    int d = dst[i];
    float x = g_ssrc[s] + g_sdst[d] + ab;
    x = (x > 0.0f) ? x : ALPHA * x;
    float ex = expf(x);
    int pos = atomicAdd(&g_cur[d], 1);
    g_rec[pos] = make_int2(s, __float_as_int(ex));
}

// ---------------------------------------------------------------------------
// K5: gather — one warp per dst node. Stream its edge records, gather
// Wh[src] rows from L2, accumulate unnormalized sum + denom in registers,
// normalize inline, single store. No float atomics anywhere.
// ---------------------------------------------------------------------------
__global__ void __launch_bounds__(256) gather_kernel(
    float* __restrict__ out, int n_nodes)
{
    int gwarp = (blockIdx.x * blockDim.x + threadIdx.x) >> 5;
    int lane = threadIdx.x & 31;
    if (gwarp >= n_nodes) return;

    int beg = g_off[gwarp];
    int cnt = g_cnt[gwarp];

    const float2* wh2 = reinterpret_cast<const float2*>(g_Wh);
    float2 acc = make_float2(0.0f, 0.0f);
    float den = 0.0f;

    for (int base = 0; base < cnt; base += 32) {
        int idx = base + lane;
        int2 rec = make_int2(0, 0);
        if (idx < cnt) rec = g_rec[beg + idx];
        int m = min(cnt - base, 32);
        #pragma unroll 4
        for (int k = 0; k < m; k++) {
            int   s  = __shfl_sync(0xffffffffu, rec.x, k);
            float ex = __int_as_float(__shfl_sync(0xffffffffu, rec.y, k));
            float2 w = __ldg(&wh2[(size_t)s * 32 + lane]);
            acc.x = fmaf(ex, w.x, acc.x);
            acc.y = fmaf(ex, w.y, acc.y);
            den += ex;
        }
    }

    float r = (den > 0.0f) ? (1.0f / den) : 1.0f;  // cnt==0 -> acc==0, matches ref
    acc.x *= r; acc.y *= r;
    reinterpret_cast<float2*>(out)[(size_t)gwarp * 32 + lane] = acc;
}

// ---------------------------------------------------------------------------
extern "C" void kernel_launch(void* const* d_in, const int* in_sizes, int n_in,
                              void* d_out, int out_size) {
    const float* h   = (const float*)d_in[0];
    const float* W   = (const float*)d_in[1];
    const float* Wb  = (const float*)d_in[2];
    const float* a   = (const float*)d_in[3];
    const float* ab  = (const float*)d_in[4];
    const int*   src = (const int*)d_in[5];
    const int*   dst = (const int*)d_in[6];
    float* out = (float*)d_out;

    int n_nodes = in_sizes[0] / F;
    int n_edges = in_sizes[5];

    zero_kernel<<<(n_nodes + 255) / 256, 256>>>(n_nodes);
    wh_kernel<<<(n_nodes + 31) / 32, 256>>>(h, W, Wb, a, n_nodes);
    count_kernel<<<(n_edges + 255) / 256, 256>>>(dst, n_edges);
    offset_kernel<<<(n_nodes + 255) / 256, 256>>>(n_nodes);
    scatter_kernel<<<(n_edges + 255) / 256, 256>>>(src, dst, ab, n_edges);
    gather_kernel<<<(n_nodes + 7) / 8, 256>>>(out, n_nodes);
}

// round 5
// speedup vs baseline: 1.4822x; 1.0770x over previous
#include <cuda_runtime.h>
#include <cuda_bf16.h>

#define N_MAX 100000
#define E_MAX 1000000
#define F 64
#define ALPHA 0.2f

// Scratch (static __device__ allocation — no cudaMalloc allowed)
__device__ float g_Wh[N_MAX * F];       // 25.6 MB (L2-resident)
__device__ float g_ssrc[N_MAX];
__device__ float g_sdst[N_MAX];
__device__ int   g_cnt[N_MAX];          // per-dst edge count
__device__ int   g_off[N_MAX];          // CSR base offset per dst
__device__ int   g_cur[N_MAX];          // scatter cursor per dst
__device__ int   g_cursor;              // global CSR allocation cursor
__device__ int2  g_rec[E_MAX];          // packed (src, ex-bits) per edge, dst-grouped

// ---------------------------------------------------------------------------
// K0: zero counters + global cursor
// ---------------------------------------------------------------------------
__global__ void zero_kernel(int n_nodes) {
    int i = blockIdx.x * blockDim.x + threadIdx.x;
    if (i < n_nodes) g_cnt[i] = 0;
    if (i == 0) g_cursor = 0;
}

// ---------------------------------------------------------------------------
// K1: Wh = h @ W^T + Wb ; s_src = Wh @ a[:F] ; s_dst = Wh @ a[F:]
// 4 nodes per warp; h rows in registers, broadcast via shfl. FFMA-pipe bound.
// ---------------------------------------------------------------------------
__global__ void __launch_bounds__(256) wh_kernel(
    const float* __restrict__ h, const float* __restrict__ W,
    const float* __restrict__ Wb, const float* __restrict__ a, int n_nodes)
{
    __shared__ float Wt[F][F + 1];   // Wt[k][j] = W[j][k]
    __shared__ float sWb[F];
    __shared__ float sa[2 * F];

    int tid = threadIdx.x;
    for (int i = tid; i < F * F; i += 256) {
        int j = i >> 6, k = i & 63;
        Wt[k][j] = W[i];
    }
    if (tid < F) sWb[tid] = Wb[tid];
    if (tid < 2 * F) sa[tid] = a[tid];
    __syncthreads();

    int warp = tid >> 5;
    int lane = tid & 31;
    int n0 = (blockIdx.x * 8 + warp) * 4;
    if (n0 >= n_nodes) return;

    float hr0[4], hr1[4];
    #pragma unroll
    for (int i = 0; i < 4; i++) {
        int n = min(n0 + i, n_nodes - 1);
        hr0[i] = h[(size_t)n * F + lane];
        hr1[i] = h[(size_t)n * F + lane + 32];
    }

    float acc0[4] = {0.f, 0.f, 0.f, 0.f};
    float acc1[4] = {0.f, 0.f, 0.f, 0.f};

    #pragma unroll
    for (int k = 0; k < 32; k++) {
        float w0 = Wt[k][lane];
        float w1 = Wt[k][lane + 32];
        #pragma unroll
        for (int i = 0; i < 4; i++) {
            float hk = __shfl_sync(0xffffffffu, hr0[i], k);
            acc0[i] = fmaf(hk, w0, acc0[i]);
            acc1[i] = fmaf(hk, w1, acc1[i]);
        }
    }
    #pragma unroll
    for (int k = 0; k < 32; k++) {
        float w0 = Wt[k + 32][lane];
        float w1 = Wt[k + 32][lane + 32];
        #pragma unroll
        for (int i = 0; i < 4; i++) {
            float hk = __shfl_sync(0xffffffffu, hr1[i], k);
            acc0[i] = fmaf(hk, w0, acc0[i]);
            acc1[i] = fmaf(hk, w1, acc1[i]);
        }
    }

    float b0 = sWb[lane], b1 = sWb[lane + 32];
    float as0 = sa[lane], as1 = sa[lane + 32];
    float ad0 = sa[F + lane], ad1 = sa[F + lane + 32];

    #pragma unroll
    for (int i = 0; i < 4; i++) {
        int n = n0 + i;
        if (n >= n_nodes) break;
        float v0 = acc0[i] + b0;
        float v1 = acc1[i] + b1;
        g_Wh[(size_t)n * F + lane]      = v0;
        g_Wh[(size_t)n * F + lane + 32] = v1;

        float p = v0 * as0 + v1 * as1;
        float q = v0 * ad0 + v1 * ad1;
        #pragma unroll
        for (int o = 16; o > 0; o >>= 1) {
            p += __shfl_down_sync(0xffffffffu, p, o);
            q += __shfl_down_sync(0xffffffffu, q, o);
        }
        if (lane == 0) {
            g_ssrc[n] = p;
            g_sdst[n] = q;
        }
    }
}

// ---------------------------------------------------------------------------
// K2: count edges per dst (int REDG, spread addresses)
// ---------------------------------------------------------------------------
__global__ void __launch_bounds__(256) count_kernel(
    const int* __restrict__ dst, int n_edges)
{
    int i = blockIdx.x * blockDim.x + threadIdx.x;
    if (i < n_edges) atomicAdd(&g_cnt[dst[i]], 1);
}

// ---------------------------------------------------------------------------
// K3: CSR offsets. 1024-thread block scan -> only ~98 global-cursor atomics.
// Segment placement order is arbitrary; per-dst contents (and output) fixed.
// ---------------------------------------------------------------------------
__global__ void __launch_bounds__(1024) offset_kernel(int n_nodes) {
    __shared__ int warp_sums[32];
    __shared__ int block_base;

    int i = blockIdx.x * 1024 + threadIdx.x;
    int lane = threadIdx.x & 31;
    int wid  = threadIdx.x >> 5;
    int c = (i < n_nodes) ? g_cnt[i] : 0;

    // warp inclusive scan
    int s = c;
    #pragma unroll
    for (int o = 1; o < 32; o <<= 1) {
        int t = __shfl_up_sync(0xffffffffu, s, o);
        if (lane >= o) s += t;
    }
    if (lane == 31) warp_sums[wid] = s;
    __syncthreads();

    if (wid == 0) {
        int v = warp_sums[lane];
        int sv = v;
        #pragma unroll
        for (int o = 1; o < 32; o <<= 1) {
            int t = __shfl_up_sync(0xffffffffu, sv, o);
            if (lane >= o) sv += t;
        }
        warp_sums[lane] = sv - v;   // exclusive warp bases
        if (lane == 31) block_base = atomicAdd(&g_cursor, sv);
    }
    __syncthreads();

    if (i < n_nodes) {
        int off = block_base + warp_sums[wid] + (s - c);
        g_off[i] = off;
        g_cur[i] = off;
    }
}

// ---------------------------------------------------------------------------
// K4: scatter — ex = exp(lrelu(s_src[src]+s_dst[dst]+ab)); claim slot in
// dst segment; write packed (src, ex). Max-shift skipped (cancels exactly).
// ---------------------------------------------------------------------------
__global__ void __launch_bounds__(256) scatter_kernel(
    const int* __restrict__ src, const int* __restrict__ dst,
    const float* __restrict__ ab_p, int n_edges)
{
    int i = blockIdx.x * blockDim.x + threadIdx.x;
    if (i >= n_edges) return;
    float ab = __ldg(ab_p);
    int s = src[i];
    int d = dst[i];
    float x = g_ssrc[s] + g_sdst[d] + ab;
    x = (x > 0.0f) ? x : ALPHA * x;
    float ex = expf(x);
    int pos = atomicAdd(&g_cur[d], 1);
    g_rec[pos] = make_int2(s, __float_as_int(ex));
}

// ---------------------------------------------------------------------------
// K5: gather — one warp per dst node, TWO edges per iteration.
// Each half-warp covers a full Wh row as 16 x float4 (256B, LDG.128).
// One shfl (computed src lane) broadcasts each half's record. Halves are
// combined with shfl_xor(16) at the end; lanes 0-15 store. No float atomics.
// ---------------------------------------------------------------------------
__global__ void __launch_bounds__(256) gather_kernel(
    float* __restrict__ out, int n_nodes)
{
    int gwarp = (blockIdx.x * blockDim.x + threadIdx.x) >> 5;
    int lane = threadIdx.x & 31;
    if (gwarp >= n_nodes) return;

    int beg = g_off[gwarp];
    int cnt = g_cnt[gwarp];
    int half = lane >> 4;
    int l16  = lane & 15;

    const float4* wh4 = reinterpret_cast<const float4*>(g_Wh);
    float4 acc = make_float4(0.f, 0.f, 0.f, 0.f);
    float den = 0.0f;

    for (int base = 0; base < cnt; base += 32) {
        int idx = base + lane;
        int2 rec = (idx < cnt) ? __ldg(&g_rec[beg + idx]) : make_int2(0, 0);
        int m = min(cnt - base, 32);
        int iters = (m + 1) >> 1;
        #pragma unroll 4
        for (int k = 0; k < iters; k++) {
            int srcLane = 2 * k + half;          // >= m -> zeroed rec -> ex=0
            int   s  = __shfl_sync(0xffffffffu, rec.x, srcLane);
            float ex = __int_as_float(__shfl_sync(0xffffffffu, rec.y, srcLane));
            float4 w = __ldg(&wh4[(size_t)s * 16 + l16]);
            acc.x = fmaf(ex, w.x, acc.x);
            acc.y = fmaf(ex, w.y, acc.y);
            acc.z = fmaf(ex, w.z, acc.z);
            acc.w = fmaf(ex, w.w, acc.w);
            den += ex;
        }
    }

    // combine the two halves (lane l <-> lane l+16 hold the same float4 slot)
    acc.x += __shfl_xor_sync(0xffffffffu, acc.x, 16);
    acc.y += __shfl_xor_sync(0xffffffffu, acc.y, 16);
    acc.z += __shfl_xor_sync(0xffffffffu, acc.z, 16);
    acc.w += __shfl_xor_sync(0xffffffffu, acc.w, 16);
    den   += __shfl_xor_sync(0xffffffffu, den,   16);

    if (half == 0) {
        float r = (den > 0.0f) ? (1.0f / den) : 1.0f;  // cnt==0 -> acc==0 == ref
        acc.x *= r; acc.y *= r; acc.z *= r; acc.w *= r;
        reinterpret_cast<float4*>(out)[(size_t)gwarp * 16 + l16] = acc;
    }
}

// ---------------------------------------------------------------------------
extern "C" void kernel_launch(void* const* d_in, const int* in_sizes, int n_in,
                              void* d_out, int out_size) {
    const float* h   = (const float*)d_in[0];
    const float* W   = (const float*)d_in[1];
    const float* Wb  = (const float*)d_in[2];
    const float* a   = (const float*)d_in[3];
    const float* ab  = (const float*)d_in[4];
    const int*   src = (const int*)d_in[5];
    const int*   dst = (const int*)d_in[6];
    float* out = (float*)d_out;

    int n_nodes = in_sizes[0] / F;
    int n_edges = in_sizes[5];

    // One-time resources, created on the (uncaptured) correctness call.
    static cudaStream_t side = nullptr;
    static cudaEvent_t evFork = nullptr, evJoin = nullptr;
    if (!side) {
        cudaStreamCreateWithFlags(&side, cudaStreamNonBlocking);
        cudaEventCreateWithFlags(&evFork, cudaEventDisableTiming);
        cudaEventCreateWithFlags(&evJoin, cudaEventDisableTiming);
    }

    // Fork: CSR prep (depends only on dst) runs beside wh (FFMA-bound).
    cudaEventRecord(evFork, 0);
    cudaStreamWaitEvent(side, evFork, 0);

    zero_kernel<<<(n_nodes + 255) / 256, 256, 0, side>>>(n_nodes);
    count_kernel<<<(n_edges + 255) / 256, 256, 0, side>>>(dst, n_edges);
    offset_kernel<<<(n_nodes + 1023) / 1024, 1024, 0, side>>>(n_nodes);
    cudaEventRecord(evJoin, side);

    wh_kernel<<<(n_nodes + 31) / 32, 256>>>(h, W, Wb, a, n_nodes);

    // Join: scatter needs both wh (scores) and CSR offsets.
    cudaStreamWaitEvent(0, evJoin, 0);
    scatter_kernel<<<(n_edges + 255) / 256, 256>>>(src, dst, ab, n_edges);
    gather_kernel<<<(n_nodes + 7) / 8, 256>>>(out, n_nodes);
}

// round 6
// speedup vs baseline: 1.5666x; 1.0569x over previous
#include <cuda_runtime.h>
#include <cuda_bf16.h>

#define N_MAX 100000
#define E_MAX 1000000
#define F 64
#define ALPHA 0.2f
#define WPAD 68   // smem row stride for W (floats): (4*lane + k) % 32 distinct

// Scratch (static __device__ allocation — no cudaMalloc allowed)
__device__ float g_Wh[N_MAX * F];       // 25.6 MB (L2-resident)
__device__ float g_ssrc[N_MAX];
__device__ float g_sdst[N_MAX];
__device__ int   g_cnt[N_MAX];          // per-dst edge count
__device__ int   g_off[N_MAX];          // CSR base offset per dst
__device__ int   g_cur[N_MAX];          // scatter cursor per dst
__device__ int   g_cursor;              // global CSR allocation cursor
__device__ int2  g_rec[E_MAX];          // packed (src, ex-bits) per edge, dst-grouped

// ---------------------------------------------------------------------------
// K0: zero counters + global cursor
// ---------------------------------------------------------------------------
__global__ void zero_kernel(int n_nodes) {
    int i = blockIdx.x * blockDim.x + threadIdx.x;
    if (i < n_nodes) g_cnt[i] = 0;
    if (i == 0) g_cursor = 0;
}

// ---------------------------------------------------------------------------
// K1: Wh = h @ W^T + Wb ; s_src = Wh @ a[:F] ; s_dst = Wh @ a[F:]
// 4 nodes per warp. NO shuffles in the mainloop: W rows ([j][k] native
// layout, padded) via conflict-free LDS.128; h values via broadcast LDS.128.
// Per 4 k-steps: 6 LDS.128 + 32 FFMA (84% FMA mix).
// ---------------------------------------------------------------------------
__global__ void __launch_bounds__(256) wh_kernel(
    const float* __restrict__ h, const float* __restrict__ W,
    const float* __restrict__ Wb, const float* __restrict__ a, int n_nodes)
{
    __shared__ float Wp[F * WPAD];          // Wp[j*WPAD + k] = W[j][k]
    __shared__ float sWb[F];
    __shared__ float sa[2 * F];
    __shared__ __align__(16) float hrow[8][4][F];   // [warp][node][k]

    int tid = threadIdx.x;
    for (int i = tid; i < F * F; i += 256) {
        int j = i >> 6, k = i & 63;
        Wp[j * WPAD + k] = W[i];
    }
    if (tid < F) sWb[tid] = Wb[tid];
    if (tid < 2 * F) sa[tid] = a[tid];

    int warp = tid >> 5;
    int lane = tid & 31;
    int n0 = (blockIdx.x * 8 + warp) * 4;

    // stage h rows for this warp's 4 nodes (clamped; extras recomputed cheap)
    #pragma unroll
    for (int i = 0; i < 4; i++) {
        int n = min(n0 + i, n_nodes - 1);
        hrow[warp][i][lane]      = h[(size_t)n * F + lane];
        hrow[warp][i][lane + 32] = h[(size_t)n * F + lane + 32];
    }
    __syncthreads();
    if (n0 >= n_nodes) return;

    const float4* w0p = reinterpret_cast<const float4*>(&Wp[lane * WPAD]);
    const float4* w1p = reinterpret_cast<const float4*>(&Wp[(lane + 32) * WPAD]);

    float acc0[4] = {0.f, 0.f, 0.f, 0.f};
    float acc1[4] = {0.f, 0.f, 0.f, 0.f};

    #pragma unroll
    for (int k4 = 0; k4 < 16; k4++) {
        float4 w0 = w0p[k4];                 // LDS.128, conflict-free
        float4 w1 = w1p[k4];
        #pragma unroll
        for (int i = 0; i < 4; i++) {
            float4 hv = reinterpret_cast<const float4*>(hrow[warp][i])[k4]; // broadcast
            acc0[i] = fmaf(hv.x, w0.x, acc0[i]);
            acc0[i] = fmaf(hv.y, w0.y, acc0[i]);
            acc0[i] = fmaf(hv.z, w0.z, acc0[i]);
            acc0[i] = fmaf(hv.w, w0.w, acc0[i]);
            acc1[i] = fmaf(hv.x, w1.x, acc1[i]);
            acc1[i] = fmaf(hv.y, w1.y, acc1[i]);
            acc1[i] = fmaf(hv.z, w1.z, acc1[i]);
            acc1[i] = fmaf(hv.w, w1.w, acc1[i]);
        }
    }

    float b0 = sWb[lane], b1 = sWb[lane + 32];
    float as0 = sa[lane], as1 = sa[lane + 32];
    float ad0 = sa[F + lane], ad1 = sa[F + lane + 32];

    #pragma unroll
    for (int i = 0; i < 4; i++) {
        int n = n0 + i;
        if (n >= n_nodes) break;
        float v0 = acc0[i] + b0;
        float v1 = acc1[i] + b1;
        g_Wh[(size_t)n * F + lane]      = v0;
        g_Wh[(size_t)n * F + lane + 32] = v1;

        float p = v0 * as0 + v1 * as1;
        float q = v0 * ad0 + v1 * ad1;
        #pragma unroll
        for (int o = 16; o > 0; o >>= 1) {
            p += __shfl_down_sync(0xffffffffu, p, o);
            q += __shfl_down_sync(0xffffffffu, q, o);
        }
        if (lane == 0) {
            g_ssrc[n] = p;
            g_sdst[n] = q;
        }
    }
}

// ---------------------------------------------------------------------------
// K2: count edges per dst (int REDG, spread addresses)
// ---------------------------------------------------------------------------
__global__ void __launch_bounds__(256) count_kernel(
    const int* __restrict__ dst, int n_edges)
{
    int i = blockIdx.x * blockDim.x + threadIdx.x;
    if (i < n_edges) atomicAdd(&g_cnt[dst[i]], 1);
}

// ---------------------------------------------------------------------------
// K3: CSR offsets. 1024-thread block scan -> only ~98 global-cursor atomics.
// Segment placement order is arbitrary; per-dst contents (and output) fixed.
// ---------------------------------------------------------------------------
__global__ void __launch_bounds__(1024) offset_kernel(int n_nodes) {
    __shared__ int warp_sums[32];
    __shared__ int block_base;

    int i = blockIdx.x * 1024 + threadIdx.x;
    int lane = threadIdx.x & 31;
    int wid  = threadIdx.x >> 5;
    int c = (i < n_nodes) ? g_cnt[i] : 0;

    int s = c;
    #pragma unroll
    for (int o = 1; o < 32; o <<= 1) {
        int t = __shfl_up_sync(0xffffffffu, s, o);
        if (lane >= o) s += t;
    }
    if (lane == 31) warp_sums[wid] = s;
    __syncthreads();

    if (wid == 0) {
        int v = warp_sums[lane];
        int sv = v;
        #pragma unroll
        for (int o = 1; o < 32; o <<= 1) {
            int t = __shfl_up_sync(0xffffffffu, sv, o);
            if (lane >= o) sv += t;
        }
        warp_sums[lane] = sv - v;
        if (lane == 31) block_base = atomicAdd(&g_cursor, sv);
    }
    __syncthreads();

    if (i < n_nodes) {
        int off = block_base + warp_sums[wid] + (s - c);
        g_off[i] = off;
        g_cur[i] = off;
    }
}

// ---------------------------------------------------------------------------
// K4: scatter — ex = exp(lrelu(s_src[src]+s_dst[dst]+ab)); claim slot in
// dst segment; write packed (src, ex). Max-shift skipped (cancels exactly).
// ---------------------------------------------------------------------------
__global__ void __launch_bounds__(256) scatter_kernel(
    const int* __restrict__ src, const int* __restrict__ dst,
    const float* __restrict__ ab_p, int n_edges)
{
    int i = blockIdx.x * blockDim.x + threadIdx.x;
    if (i >= n_edges) return;
    float ab = __ldg(ab_p);
    int s = src[i];
    int d = dst[i];
    float x = g_ssrc[s] + g_sdst[d] + ab;
    x = (x > 0.0f) ? x : ALPHA * x;
    float ex = expf(x);
    int pos = atomicAdd(&g_cur[d], 1);
    g_rec[pos] = make_int2(s, __float_as_int(ex));
}

// ---------------------------------------------------------------------------
// K5: gather — one warp per dst node, TWO edges per iteration.
// Each half-warp covers a full Wh row as 16 x float4 (LDG.128 from L2).
// ---------------------------------------------------------------------------
__global__ void __launch_bounds__(256) gather_kernel(
    float* __restrict__ out, int n_nodes)
{
    int gwarp = (blockIdx.x * blockDim.x + threadIdx.x) >> 5;
    int lane = threadIdx.x & 31;
    if (gwarp >= n_nodes) return;

    int beg = g_off[gwarp];
    int cnt = g_cnt[gwarp];
    int half = lane >> 4;
    int l16  = lane & 15;

    const float4* wh4 = reinterpret_cast<const float4*>(g_Wh);
    float4 acc = make_float4(0.f, 0.f, 0.f, 0.f);
    float den = 0.0f;

    for (int base = 0; base < cnt; base += 32) {
        int idx = base + lane;
        int2 rec = (idx < cnt) ? __ldg(&g_rec[beg + idx]) : make_int2(0, 0);
        int m = min(cnt - base, 32);
        int iters = (m + 1) >> 1;
        #pragma unroll 4
        for (int k = 0; k < iters; k++) {
            int srcLane = 2 * k + half;          // >= m -> zeroed rec -> ex=0
            int   s  = __shfl_sync(0xffffffffu, rec.x, srcLane);
            float ex = __int_as_float(__shfl_sync(0xffffffffu, rec.y, srcLane));
            float4 w = __ldg(&wh4[(size_t)s * 16 + l16]);
            acc.x = fmaf(ex, w.x, acc.x);
            acc.y = fmaf(ex, w.y, acc.y);
            acc.z = fmaf(ex, w.z, acc.z);
            acc.w = fmaf(ex, w.w, acc.w);
            den += ex;
        }
    }

    acc.x += __shfl_xor_sync(0xffffffffu, acc.x, 16);
    acc.y += __shfl_xor_sync(0xffffffffu, acc.y, 16);
    acc.z += __shfl_xor_sync(0xffffffffu, acc.z, 16);
    acc.w += __shfl_xor_sync(0xffffffffu, acc.w, 16);
    den   += __shfl_xor_sync(0xffffffffu, den,   16);

    if (half == 0) {
        float r = (den > 0.0f) ? (1.0f / den) : 1.0f;  // cnt==0 -> acc==0 == ref
        acc.x *= r; acc.y *= r; acc.z *= r; acc.w *= r;
        reinterpret_cast<float4*>(out)[(size_t)gwarp * 16 + l16] = acc;
    }
}

// ---------------------------------------------------------------------------
extern "C" void kernel_launch(void* const* d_in, const int* in_sizes, int n_in,
                              void* d_out, int out_size) {
    const float* h   = (const float*)d_in[0];
    const float* W   = (const float*)d_in[1];
    const float* Wb  = (const float*)d_in[2];
    const float* a   = (const float*)d_in[3];
    const float* ab  = (const float*)d_in[4];
    const int*   src = (const int*)d_in[5];
    const int*   dst = (const int*)d_in[6];
    float* out = (float*)d_out;

    int n_nodes = in_sizes[0] / F;
    int n_edges = in_sizes[5];

    static cudaStream_t side = nullptr;
    static cudaEvent_t evFork = nullptr, evJoin = nullptr;
    if (!side) {
        cudaStreamCreateWithFlags(&side, cudaStreamNonBlocking);
        cudaEventCreateWithFlags(&evFork, cudaEventDisableTiming);
        cudaEventCreateWithFlags(&evJoin, cudaEventDisableTiming);
    }

    // Fork: CSR prep (depends only on dst) runs beside wh (FFMA-bound).
    cudaEventRecord(evFork, 0);
    cudaStreamWaitEvent(side, evFork, 0);

    zero_kernel<<<(n_nodes + 255) / 256, 256, 0, side>>>(n_nodes);
    count_kernel<<<(n_edges + 255) / 256, 256, 0, side>>>(dst, n_edges);
    offset_kernel<<<(n_nodes + 1023) / 1024, 1024, 0, side>>>(n_nodes);
    cudaEventRecord(evJoin, side);

    wh_kernel<<<(n_nodes + 31) / 32, 256>>>(h, W, Wb, a, n_nodes);

    cudaStreamWaitEvent(0, evJoin, 0);
    scatter_kernel<<<(n_edges + 255) / 256, 256>>>(src, dst, ab, n_edges);
    gather_kernel<<<(n_nodes + 7) / 8, 256>>>(out, n_nodes);
}